// round 11
// baseline (speedup 1.0000x reference)
#include <cuda_runtime.h>
#include <cuda_bf16.h>
#include <cstdint>
#include <math.h>

#define Bb     4
#define NN     65536
#define CC     192
#define NHEADS 6
#define HC     32
#define BN     (Bb * NN)
#define NBLK   512            /* qkv row-chunks per batch: 65536/128 */

typedef unsigned long long u64;
typedef unsigned int       u32;

// ---------------- packed f32x2 helpers -------------------------------------
__device__ __forceinline__ u64 pack2dup(float x) {
    u64 r; asm("mov.b64 %0, {%1,%1};" : "=l"(r) : "f"(x)); return r;
}
__device__ __forceinline__ float2 unpack2(u64 v) {
    float2 r; asm("mov.b64 {%0,%1}, %2;" : "=f"(r.x), "=f"(r.y) : "l"(v)); return r;
}
__device__ __forceinline__ void fma2(u64& d, u64 a, u64 b) {
    asm("fma.rn.f32x2 %0, %1, %2, %0;" : "+l"(d) : "l"(a), "l"(b));
}
__device__ __forceinline__ void split_bf16(float v, __nv_bfloat16& h, __nv_bfloat16& l) {
    h = __float2bfloat16(v);
    l = __float2bfloat16(v - __bfloat162float(h));
}
__device__ __forceinline__ u32 packbf(float a, float b) {
    __nv_bfloat162 t = __floats2bfloat162_rn(a, b);   // low half = a
    return *reinterpret_cast<u32*>(&t);
}

// mma.sync m16n8k16 row.col bf16 -> f32 accum (sm_80+ base feature)
__device__ __forceinline__ void mma_bf16(float* d, const u32* a, u32 b0, u32 b1) {
    asm volatile(
        "mma.sync.aligned.m16n8k16.row.col.f32.bf16.bf16.f32 "
        "{%0,%1,%2,%3}, {%4,%5,%6,%7}, {%8,%9}, {%0,%1,%2,%3};"
        : "+f"(d[0]), "+f"(d[1]), "+f"(d[2]), "+f"(d[3])
        : "r"(a[0]), "r"(a[1]), "r"(a[2]), "r"(a[3]), "r"(b0), "r"(b1));
}

// ---------------- global scratch -------------------------------------------
__device__ float g_q  [(size_t)BN * CC];
__device__ float g_kv [Bb * NHEADS * HC * HC];
__device__ float g_kvp[(size_t)Bb * NHEADS * NBLK * HC * HC];  // per-block partials
__device__ __nv_bfloat16 g_h_hi  [(size_t)BN * CC];
__device__ __nv_bfloat16 g_h_lo  [(size_t)BN * CC];
// B fragments, layout [..gnt..][kt][lane][hl] so hi+lo load as one LDG.128.
// u64 = {b0pair(k,k+1), b1pair(k+8,k+9)}
__device__ u64 g_fq[6 * 12 * 12 * 32 * 2];   // [h][gnt12][kt12][lane][hl]
__device__ u64 g_f1[24 * 12 * 32 * 2];       // [gnt24][kt12][lane][hl]
__device__ u64 g_f2[24 * 12 * 32 * 2];

// ---------------------------------------------------------------------------
// prep: build B fragments (hi / lo split) for all three weight matrices.
__global__ __launch_bounds__(256) void k_prep(const float* __restrict__ qkv_w,
                                              const float* __restrict__ o1_w,
                                              const float* __restrict__ o2_w) {
    int i = blockIdx.x * 256 + threadIdx.x;
    const int NQ = 6 * 12 * 12 * 32 * 2;      // 55296
    const int NM = 24 * 12 * 32 * 2;          // 18432
    const float* W; u64* dst; int j, k, hl;
    if (i < NQ) {
        hl = i & 1; int lane = (i >> 1) & 31; int q = i >> 6;
        int kt = q % 12; q /= 12;
        int gnt = q % 12; int h = q / 12;
        j = 96 * h + gnt * 8 + (lane >> 2);
        k = kt * 16 + 2 * (lane & 3);
        W = qkv_w; dst = g_fq + i;
    } else if (i < NQ + NM) {
        int t = i - NQ;
        hl = t & 1; int lane = (t >> 1) & 31; int q = t >> 6;
        int kt = q % 12; int gnt = q / 12;
        j = gnt * 8 + (lane >> 2);
        k = kt * 16 + 2 * (lane & 3);
        W = o1_w; dst = g_f1 + t;
    } else if (i < NQ + 2 * NM) {
        int t = i - NQ - NM;
        hl = t & 1; int lane = (t >> 1) & 31; int q = t >> 6;
        int kt = q % 12; int gnt = q / 12;
        j = gnt * 8 + (lane >> 2);
        k = kt * 16 + 2 * (lane & 3);
        W = o2_w; dst = g_f2 + t;
    } else return;

    float w[4] = { W[(size_t)j * 192 + k],     W[(size_t)j * 192 + k + 1],
                   W[(size_t)j * 192 + k + 8], W[(size_t)j * 192 + k + 9] };
    float v[4];
    #pragma unroll
    for (int e = 0; e < 4; ++e) {
        __nv_bfloat16 hb, lb; split_bf16(w[e], hb, lb);
        v[e] = hl ? __bfloat162float(lb) : __bfloat162float(hb);
    }
    u32 p0 = packbf(v[0], v[1]);
    u32 p1 = packbf(v[2], v[3]);
    *dst = (u64)p0 | ((u64)p1 << 32);
}

// deterministic kv reduction: one block per (b,h); thread = (d,e); fixed order
__global__ __launch_bounds__(1024) void k_kvred() {
    int bh = blockIdx.x;            // 0..23
    int de = threadIdx.x;           // 0..1023
    const float* src = g_kvp + (size_t)bh * NBLK * 1024 + de;
    float s = 0.0f;
    for (int i = 0; i < NBLK; ++i) s += src[(size_t)i * 1024];
    g_kv[bh * 1024 + de] = s;
}

// ====================== k_qkv: mma.sync QKV + LN + kv ======================
// (unchanged from round-10 passing kernel)
#define QS_TOT ((12800 + 12800 + 128 * 66 + 576 + 768) * 4)   /* 141568 B */

__global__ __launch_bounds__(512) void k_qkv(
    const float* __restrict__ x, const float* __restrict__ qkv_b,
    const float* __restrict__ klw, const float* __restrict__ klb,
    const float* __restrict__ vlw, const float* __restrict__ vlb)
{
    extern __shared__ float smf[];
    u32*  AsHi  = (u32*)smf;                 // [128][100]
    u32*  AsLo  = AsHi + 12800;
    float* kvbuf = smf + 25600;              // [128][66]
    float* sqb   = kvbuf + 128 * 66;         // 576
    float* sln   = sqb + 576;                // klw|klb|vlw|vlb each 192

    const int tid  = threadIdx.x;
    const int lane = tid & 31, warp = tid >> 5;
    const int rg = warp & 7, ch = warp >> 3;
    const int tig = lane & 3, gid = lane >> 2;
    const size_t R0 = (size_t)blockIdx.x * 128;
    const int b   = blockIdx.x >> 9;
    const int blk = blockIdx.x & (NBLK - 1);

    for (int i = tid; i < 576; i += 512) sqb[i] = qkv_b[i];
    for (int i = tid; i < 192; i += 512) {
        sln[i] = klw[i]; sln[192 + i] = klb[i];
        sln[384 + i] = vlw[i]; sln[576 + i] = vlb[i];
    }
    const float2* xsrc = reinterpret_cast<const float2*>(x + R0 * CC);
    for (int i = tid; i < 128 * 96; i += 512) {
        int r = i / 96, c = i - r * 96;
        float2 v = xsrc[i];
        __nv_bfloat16 h0, l0, h1, l1;
        split_bf16(v.x, h0, l0); split_bf16(v.y, h1, l1);
        AsHi[r * 100 + c] = ((u32)__bfloat16_as_ushort(h1) << 16) | __bfloat16_as_ushort(h0);
        AsLo[r * 100 + c] = ((u32)__bfloat16_as_ushort(l1) << 16) | __bfloat16_as_ushort(l0);
    }
    __syncthreads();

    const int arow = rg * 16 + gid;
    const u32* AH0 = AsHi + arow * 100;
    const u32* AH8 = AsHi + (arow + 8) * 100;
    const u32* AL0 = AsLo + arow * 100;
    const u32* AL8 = AsLo + (arow + 8) * 100;

    for (int h = 0; h < NHEADS; ++h) {
        float acc[6][4];
        #pragma unroll
        for (int nt = 0; nt < 6; ++nt)
            #pragma unroll
            for (int e = 0; e < 4; ++e) acc[nt][e] = 0.0f;

        const ulonglong2* fh =
            reinterpret_cast<const ulonglong2*>(g_fq + (size_t)h * (12 * 12 * 32 * 2));
        for (int kt = 0; kt < 12; ++kt) {
            int kb = kt * 8 + tig;
            u32 ah[4] = { AH0[kb], AH8[kb], AH0[kb + 4], AH8[kb + 4] };
            u32 al[4] = { AL0[kb], AL8[kb], AL0[kb + 4], AL8[kb + 4] };
            #pragma unroll
            for (int nt = 0; nt < 6; ++nt) {
                int gnt = ch * 6 + nt;
                ulonglong2 f = fh[(gnt * 12 + kt) * 32 + lane];
                u32 bh0 = (u32)f.x, bh1 = (u32)(f.x >> 32);
                u32 bl0 = (u32)f.y, bl1 = (u32)(f.y >> 32);
                mma_bf16(acc[nt], ah, bh0, bh1);
                mma_bf16(acc[nt], ah, bl0, bl1);
                mma_bf16(acc[nt], al, bh0, bh1);
            }
        }
        __syncthreads();

        #pragma unroll
        for (int nt = 0; nt < 6; ++nt) {
            int col = ch * 48 + nt * 8 + 2 * tig;
            float b0 = sqb[96 * h + col], b1 = sqb[96 * h + col + 1];
            float c0 = acc[nt][0] + b0, c1 = acc[nt][1] + b1;
            float c2 = acc[nt][2] + b0, c3 = acc[nt][3] + b1;
            if (col < 32) {
                float* q0 = g_q + (R0 + arow) * CC + h * HC + col;
                float* q8 = g_q + (R0 + arow + 8) * CC + h * HC + col;
                *reinterpret_cast<float2*>(q0) = make_float2(c0, c1);
                *reinterpret_cast<float2*>(q8) = make_float2(c2, c3);
            } else {
                int kc = col - 32;
                *reinterpret_cast<float2*>(kvbuf + arow * 66 + kc)       = make_float2(c0, c1);
                *reinterpret_cast<float2*>(kvbuf + (arow + 8) * 66 + kc) = make_float2(c2, c3);
            }
        }
        __syncthreads();

        if (tid < 256) {
            int row = tid & 127, isv = tid >> 7;
            float* p = kvbuf + row * 66 + isv * 32;
            const float* lw = sln + isv * 384 + h * HC;
            const float* lb = lw + 192;
            float s = 0.0f;
            #pragma unroll
            for (int i = 0; i < 32; ++i) s += p[i];
            float mean = s * (1.0f / 32.0f), vs = 0.0f;
            #pragma unroll
            for (int i = 0; i < 32; ++i) { float d = p[i] - mean; vs = fmaf(d, d, vs); }
            float inv = 1.0f / (sqrtf(vs * (1.0f / 31.0f)) + 1e-5f);
            #pragma unroll
            for (int i = 0; i < 32; ++i)
                p[i] = fmaf(lw[i], (p[i] - mean) * inv, lb[i]);
        }
        __syncthreads();

        {
            int d  = tid >> 4;
            int e0 = (tid & 15) << 1;
            u64 s01 = 0ull;
            for (int r = 0; r < 128; ++r) {
                u64 kk = pack2dup(kvbuf[r * 66 + d]);
                u64 vv = *reinterpret_cast<const u64*>(kvbuf + r * 66 + 32 + e0);
                fma2(s01, kk, vv);
            }
            float2 a = unpack2(s01);
            float* dst = g_kvp + ((size_t)((b * NHEADS) + h) * NBLK + blk) * 1024
                       + d * HC + e0;
            *reinterpret_cast<float2*>(dst) = make_float2(a.x, a.y);
        }
    }
}

// ====== k_amlp1: fused (ret = q@kv/N + x) -> split bf16 -> o1 GEMM + GELU ===
// 512 threads, 128 rows/block.
// SMEM: AsHi[128][100]u32 | AsLo (phase-1 alias: qscr[128][196] fp32)
//       | kvs[192][34] fp32 | sbv[192]
#define AM_KV   25600                        /* float offset of kvs   */
#define AM_BV   (AM_KV + 192 * 34)           /* float offset of sbv   */
#define AM_TOT  ((AM_BV + 192) * 4)          /* 132352 B              */

__global__ __launch_bounds__(512) void k_amlp1(const float* __restrict__ x,
                                               const float* __restrict__ bias)
{
    extern __shared__ float smf[];
    u32*  AsHi = (u32*)smf;            // [128][100]
    u32*  AsLo = AsHi + 12800;
    float* qscr = smf;                 // alias: [128][196] fp32 (phase 1 only)
    float* kvs  = smf + AM_KV;         // [192][34] padded
    float* sbv  = smf + AM_BV;         // 192

    const int tid  = threadIdx.x;
    const int lane = tid & 31, warp = tid >> 5;
    const int rg = warp & 7, ch = warp >> 3;
    const int tig = lane & 3, gid = lane >> 2;
    const size_t R0 = (size_t)blockIdx.x * 128;
    const int b = blockIdx.x >> 9;     // 512 blocks per batch

    if (tid < 192) sbv[tid] = bias[tid];
    // kv (scaled), padded stride 34
    for (int i = tid; i < NHEADS * HC * HC; i += 512) {
        int row = i >> 5, e = i & 31;
        kvs[row * 34 + e] = g_kv[b * (NHEADS * HC * HC) + i] * (1.0f / (float)NN);
    }
    // q rows -> qscr (stride 196)
    {
        const float* qsrc = g_q + R0 * CC;
        for (int i = tid; i < 128 * 192; i += 512) {
            int r = i / 192, c = i - r * 192;
            qscr[r * 196 + c] = qsrc[i];
        }
    }
    __syncthreads();

    // phase 2: thread (r = tid>>2, cq = tid&3) computes ret[48] = q@kv for
    // cols [cq*48, cq*48+48), accumulated as 24 packed f32x2 pairs.
    const int r  = tid >> 2;
    const int c0 = (tid & 3) * 48;
    u64 acc2[24];
    #pragma unroll
    for (int i = 0; i < 24; ++i) acc2[i] = 0ull;
    {
        const float* qrow = qscr + r * 196;
        for (int d = 0; d < 32; ++d) {
            // up to 2 heads span this 48-col range
            int hA = c0 >> 5, hB = (c0 + 47) >> 5;
            u64 qA = pack2dup(qrow[hA * 32 + d]);
            u64 qB = pack2dup(qrow[hB * 32 + d]);
            #pragma unroll
            for (int pi = 0; pi < 24; ++pi) {
                int c = c0 + 2 * pi;
                int h = c >> 5;
                u64 kvp = *reinterpret_cast<const u64*>(kvs + (h * 32 + d) * 34 + (c & 31));
                fma2(acc2[pi], (h == hA) ? qA : qB, kvp);
            }
        }
    }
    __syncthreads();   // all qscr reads done; AsHi/AsLo writable

    // phase 3: ret + x -> split bf16 hi/lo into AsHi/AsLo
    {
        const float* xrow = x + (R0 + r) * CC + c0;
        #pragma unroll
        for (int pi = 0; pi < 24; ++pi) {
            float2 a = unpack2(acc2[pi]);
            float v0 = a.x + xrow[2 * pi];
            float v1 = a.y + xrow[2 * pi + 1];
            __nv_bfloat16 h0, l0, h1, l1;
            split_bf16(v0, h0, l0); split_bf16(v1, h1, l1);
            AsHi[r * 100 + (c0 >> 1) + pi] =
                ((u32)__bfloat16_as_ushort(h1) << 16) | __bfloat16_as_ushort(h0);
            AsLo[r * 100 + (c0 >> 1) + pi] =
                ((u32)__bfloat16_as_ushort(l1) << 16) | __bfloat16_as_ushort(l0);
        }
    }
    __syncthreads();

    // phase 4: o1 GEMM (bf16x3) + bias + exact GELU -> g_h_hi/lo
    const int arow = rg * 16 + gid;
    const u32* AH0 = AsHi + arow * 100;
    const u32* AH8 = AsHi + (arow + 8) * 100;
    const u32* AL0 = AsLo + arow * 100;
    const u32* AL8 = AsLo + (arow + 8) * 100;

    float acc[12][4];
    #pragma unroll
    for (int nt = 0; nt < 12; ++nt)
        #pragma unroll
        for (int e = 0; e < 4; ++e) acc[nt][e] = 0.0f;

    const ulonglong2* fr = reinterpret_cast<const ulonglong2*>(g_f1);
    for (int kt = 0; kt < 12; ++kt) {
        int kb = kt * 8 + tig;
        u32 ah[4] = { AH0[kb], AH8[kb], AH0[kb + 4], AH8[kb + 4] };
        u32 al[4] = { AL0[kb], AL8[kb], AL0[kb + 4], AL8[kb + 4] };
        #pragma unroll
        for (int nt = 0; nt < 12; ++nt) {
            int gnt = ch * 12 + nt;
            ulonglong2 f = fr[(gnt * 12 + kt) * 32 + lane];
            u32 bh0 = (u32)f.x, bh1 = (u32)(f.x >> 32);
            u32 bl0 = (u32)f.y, bl1 = (u32)(f.y >> 32);
            mma_bf16(acc[nt], ah, bh0, bh1);
            mma_bf16(acc[nt], ah, bl0, bl1);
            mma_bf16(acc[nt], al, bh0, bh1);
        }
    }

    #pragma unroll
    for (int nt = 0; nt < 12; ++nt) {
        int col = ch * 96 + nt * 8 + 2 * tig;
        float b0 = sbv[col], b1 = sbv[col + 1];
        float v0 = acc[nt][0] + b0, v1 = acc[nt][1] + b1;
        float v2 = acc[nt][2] + b0, v3 = acc[nt][3] + b1;
        size_t g0 = (R0 + arow) * CC + col;
        size_t g8 = (R0 + arow + 8) * CC + col;
        float e0 = 0.5f * v0 * (1.0f + erff(v0 * 0.70710678118654752440f));
        float e1 = 0.5f * v1 * (1.0f + erff(v1 * 0.70710678118654752440f));
        float e2 = 0.5f * v2 * (1.0f + erff(v2 * 0.70710678118654752440f));
        float e3 = 0.5f * v3 * (1.0f + erff(v3 * 0.70710678118654752440f));
        __nv_bfloat16 h0, l0, h1, l1, h2, l2, h3, l3;
        split_bf16(e0, h0, l0); split_bf16(e1, h1, l1);
        split_bf16(e2, h2, l2); split_bf16(e3, h3, l3);
        *reinterpret_cast<u32*>(g_h_hi + g0) = ((u32)__bfloat16_as_ushort(h1) << 16) | __bfloat16_as_ushort(h0);
        *reinterpret_cast<u32*>(g_h_lo + g0) = ((u32)__bfloat16_as_ushort(l1) << 16) | __bfloat16_as_ushort(l0);
        *reinterpret_cast<u32*>(g_h_hi + g8) = ((u32)__bfloat16_as_ushort(h3) << 16) | __bfloat16_as_ushort(h2);
        *reinterpret_cast<u32*>(g_h_lo + g8) = ((u32)__bfloat16_as_ushort(l3) << 16) | __bfloat16_as_ushort(l2);
    }
}

// ====================== k_mlp2: o2 GEMM + bias + x residual ================
#define MS_TOT ((12800 + 12800 + 192) * 4)   /* 103168 B */

__global__ __launch_bounds__(512) void k_mlp2(const float* __restrict__ bias,
                                              const float* __restrict__ xres,
                                              float* __restrict__ Ofp)
{
    extern __shared__ float smf[];
    u32*  AsHi = (u32*)smf;            // [128][100]
    u32*  AsLo = AsHi + 12800;
    float* sbv = smf + 25600;          // 192 floats

    const int tid  = threadIdx.x;
    const int lane = tid & 31, warp = tid >> 5;
    const int rg = warp & 7, ch = warp >> 3;
    const int tig = lane & 3, gid = lane >> 2;
    const size_t R0 = (size_t)blockIdx.x * 128;

    if (tid < 192) sbv[tid] = bias[tid];
    for (int i = tid; i < 128 * 24; i += 512) {
        int r = i / 24, c4 = i - r * 24;
        uint4 vh = reinterpret_cast<const uint4*>(g_h_hi + (R0 + r) * CC)[c4];
        uint4 vl = reinterpret_cast<const uint4*>(g_h_lo + (R0 + r) * CC)[c4];
        reinterpret_cast<uint4*>(AsHi + r * 100)[c4] = vh;
        reinterpret_cast<uint4*>(AsLo + r * 100)[c4] = vl;
    }
    __syncthreads();

    const int arow = rg * 16 + gid;
    const u32* AH0 = AsHi + arow * 100;
    const u32* AH8 = AsHi + (arow + 8) * 100;
    const u32* AL0 = AsLo + arow * 100;
    const u32* AL8 = AsLo + (arow + 8) * 100;

    float acc[12][4];
    #pragma unroll
    for (int nt = 0; nt < 12; ++nt)
        #pragma unroll
        for (int e = 0; e < 4; ++e) acc[nt][e] = 0.0f;

    const ulonglong2* fr = reinterpret_cast<const ulonglong2*>(g_f2);
    for (int kt = 0; kt < 12; ++kt) {
        int kb = kt * 8 + tig;
        u32 ah[4] = { AH0[kb], AH8[kb], AH0[kb + 4], AH8[kb + 4] };
        u32 al[4] = { AL0[kb], AL8[kb], AL0[kb + 4], AL8[kb + 4] };
        #pragma unroll
        for (int nt = 0; nt < 12; ++nt) {
            int gnt = ch * 12 + nt;
            ulonglong2 f = fr[(gnt * 12 + kt) * 32 + lane];
            u32 bh0 = (u32)f.x, bh1 = (u32)(f.x >> 32);
            u32 bl0 = (u32)f.y, bl1 = (u32)(f.y >> 32);
            mma_bf16(acc[nt], ah, bh0, bh1);
            mma_bf16(acc[nt], ah, bl0, bl1);
            mma_bf16(acc[nt], al, bh0, bh1);
        }
    }

    #pragma unroll
    for (int nt = 0; nt < 12; ++nt) {
        int col = ch * 96 + nt * 8 + 2 * tig;
        float b0 = sbv[col], b1 = sbv[col + 1];
        float v0 = acc[nt][0] + b0, v1 = acc[nt][1] + b1;
        float v2 = acc[nt][2] + b0, v3 = acc[nt][3] + b1;
        size_t g0 = (R0 + arow) * CC + col;
        size_t g8 = (R0 + arow + 8) * CC + col;
        float2 x0 = *reinterpret_cast<const float2*>(xres + g0);
        float2 x8 = *reinterpret_cast<const float2*>(xres + g8);
        *reinterpret_cast<float2*>(Ofp + g0) = make_float2(v0 + x0.x, v1 + x0.y);
        *reinterpret_cast<float2*>(Ofp + g8) = make_float2(v2 + x8.x, v3 + x8.y);
    }
}

// ---------------------------------------------------------------------------
extern "C" void kernel_launch(void* const* d_in, const int* in_sizes, int n_in,
                              void* d_out, int out_size)
{
    (void)in_sizes; (void)n_in; (void)out_size;
    const float* x     = (const float*)d_in[0];
    const float* qkv_w = (const float*)d_in[1];
    const float* qkv_b = (const float*)d_in[2];
    const float* o1_w  = (const float*)d_in[3];
    const float* o1_b  = (const float*)d_in[4];
    const float* o2_w  = (const float*)d_in[5];
    const float* o2_b  = (const float*)d_in[6];
    const float* klw   = (const float*)d_in[7];
    const float* klb   = (const float*)d_in[8];
    const float* vlw   = (const float*)d_in[9];
    const float* vlb   = (const float*)d_in[10];
    float* out = (float*)d_out;

    cudaFuncSetAttribute(k_qkv,   cudaFuncAttributeMaxDynamicSharedMemorySize, QS_TOT);
    cudaFuncSetAttribute(k_amlp1, cudaFuncAttributeMaxDynamicSharedMemorySize, AM_TOT);
    cudaFuncSetAttribute(k_mlp2,  cudaFuncAttributeMaxDynamicSharedMemorySize, MS_TOT);

    k_prep<<<360, 256>>>(qkv_w, o1_w, o2_w);

    k_qkv<<<BN / 128, 512, QS_TOT>>>(x, qkv_b, klw, klb, vlw, vlb);
    k_kvred<<<Bb * NHEADS, 1024>>>();
    k_amlp1<<<BN / 128, 512, AM_TOT>>>(x, o1_b);
    k_mlp2<<<BN / 128, 512, MS_TOT>>>(o2_b, x, out);
}

// round 16
// speedup vs baseline: 1.3375x; 1.3375x over previous
#include <cuda_runtime.h>
#include <cuda_bf16.h>
#include <cstdint>
#include <math.h>

#define Bb     4
#define NN     65536
#define CC     192
#define NHEADS 6
#define HC     32
#define BN     (Bb * NN)
#define NBLK   512            /* qkv row-chunks per batch: 65536/128 */

typedef unsigned long long u64;
typedef unsigned int       u32;

// ---------------- packed f32x2 helpers -------------------------------------
__device__ __forceinline__ u64 pack2dup(float x) {
    u64 r; asm("mov.b64 %0, {%1,%1};" : "=l"(r) : "f"(x)); return r;
}
__device__ __forceinline__ float2 unpack2(u64 v) {
    float2 r; asm("mov.b64 {%0,%1}, %2;" : "=f"(r.x), "=f"(r.y) : "l"(v)); return r;
}
__device__ __forceinline__ void fma2(u64& d, u64 a, u64 b) {
    asm("fma.rn.f32x2 %0, %1, %2, %0;" : "+l"(d) : "l"(a), "l"(b));
}
__device__ __forceinline__ void split_bf16(float v, __nv_bfloat16& h, __nv_bfloat16& l) {
    h = __float2bfloat16(v);
    l = __float2bfloat16(v - __bfloat162float(h));
}
__device__ __forceinline__ u32 packbf(float a, float b) {
    __nv_bfloat162 t = __floats2bfloat162_rn(a, b);   // low half = a
    return *reinterpret_cast<u32*>(&t);
}

// mma.sync m16n8k16 row.col bf16 -> f32 accum (sm_80+ base feature)
__device__ __forceinline__ void mma_bf16(float* d, const u32* a, u32 b0, u32 b1) {
    asm volatile(
        "mma.sync.aligned.m16n8k16.row.col.f32.bf16.bf16.f32 "
        "{%0,%1,%2,%3}, {%4,%5,%6,%7}, {%8,%9}, {%0,%1,%2,%3};"
        : "+f"(d[0]), "+f"(d[1]), "+f"(d[2]), "+f"(d[3])
        : "r"(a[0]), "r"(a[1]), "r"(a[2]), "r"(a[3]), "r"(b0), "r"(b1));
}
// 3-pass split-bf16 MMA on one fragment pair (hi in f.x, lo in f.y)
__device__ __forceinline__ void mma3(float* acc, const u32* ah, const u32* al,
                                     ulonglong2 f) {
    u32 bh0 = (u32)f.x, bh1 = (u32)(f.x >> 32);
    u32 bl0 = (u32)f.y, bl1 = (u32)(f.y >> 32);
    mma_bf16(acc, ah, bh0, bh1);
    mma_bf16(acc, ah, bl0, bl1);
    mma_bf16(acc, al, bh0, bh1);
}

// ---------------- global scratch -------------------------------------------
__device__ float g_q  [(size_t)BN * CC];
__device__ float g_kv [Bb * NHEADS * HC * HC];
__device__ float g_kvp[(size_t)Bb * NHEADS * NBLK * HC * HC];  // per-block partials
__device__ __nv_bfloat16 g_ret_hi[(size_t)BN * CC];
__device__ __nv_bfloat16 g_ret_lo[(size_t)BN * CC];
__device__ __nv_bfloat16 g_h_hi  [(size_t)BN * CC];
__device__ __nv_bfloat16 g_h_lo  [(size_t)BN * CC];
// B fragments, layout [..gnt..][kt][lane][hl]; u64 = {pair(k,k+1), pair(k+8,k+9)}
__device__ u64 g_fq[6 * 12 * 12 * 32 * 2];   // [h][gnt12][kt12][lane][hl]
__device__ u64 g_f1[24 * 12 * 32 * 2];       // [gnt24][kt12][lane][hl]
__device__ u64 g_f2[24 * 12 * 32 * 2];

// ---------------------------------------------------------------------------
__global__ __launch_bounds__(256) void k_prep(const float* __restrict__ qkv_w,
                                              const float* __restrict__ o1_w,
                                              const float* __restrict__ o2_w) {
    int i = blockIdx.x * 256 + threadIdx.x;
    const int NQ = 6 * 12 * 12 * 32 * 2;      // 55296
    const int NM = 24 * 12 * 32 * 2;          // 18432
    const float* W; u64* dst; int j, k, hl;
    if (i < NQ) {
        hl = i & 1; int lane = (i >> 1) & 31; int q = i >> 6;
        int kt = q % 12; q /= 12;
        int gnt = q % 12; int h = q / 12;
        j = 96 * h + gnt * 8 + (lane >> 2);
        k = kt * 16 + 2 * (lane & 3);
        W = qkv_w; dst = g_fq + i;
    } else if (i < NQ + NM) {
        int t = i - NQ;
        hl = t & 1; int lane = (t >> 1) & 31; int q = t >> 6;
        int kt = q % 12; int gnt = q / 12;
        j = gnt * 8 + (lane >> 2);
        k = kt * 16 + 2 * (lane & 3);
        W = o1_w; dst = g_f1 + t;
    } else if (i < NQ + 2 * NM) {
        int t = i - NQ - NM;
        hl = t & 1; int lane = (t >> 1) & 31; int q = t >> 6;
        int kt = q % 12; int gnt = q / 12;
        j = gnt * 8 + (lane >> 2);
        k = kt * 16 + 2 * (lane & 3);
        W = o2_w; dst = g_f2 + t;
    } else return;

    float w[4] = { W[(size_t)j * 192 + k],     W[(size_t)j * 192 + k + 1],
                   W[(size_t)j * 192 + k + 8], W[(size_t)j * 192 + k + 9] };
    float v[4];
    #pragma unroll
    for (int e = 0; e < 4; ++e) {
        __nv_bfloat16 hb, lb; split_bf16(w[e], hb, lb);
        v[e] = hl ? __bfloat162float(lb) : __bfloat162float(hb);
    }
    u32 p0 = packbf(v[0], v[1]);
    u32 p1 = packbf(v[2], v[3]);
    *dst = (u64)p0 | ((u64)p1 << 32);
}

// deterministic kv reduction: one block per (b,h); thread = (d,e); fixed order
__global__ __launch_bounds__(1024) void k_kvred() {
    int bh = blockIdx.x;
    int de = threadIdx.x;
    const float* src = g_kvp + (size_t)bh * NBLK * 1024 + de;
    float s = 0.0f;
    for (int i = 0; i < NBLK; ++i) s += src[(size_t)i * 1024];
    g_kv[bh * 1024 + de] = s;
}

// ====================== k_qkv: mma.sync QKV + LN + kv ======================
// Round-10 structure; kt loop software-pipelined (prefetch next-kt frags).
#define QS_TOT ((12800 + 12800 + 128 * 66 + 576 + 768) * 4)   /* 141568 B */

__global__ __launch_bounds__(512) void k_qkv(
    const float* __restrict__ x, const float* __restrict__ qkv_b,
    const float* __restrict__ klw, const float* __restrict__ klb,
    const float* __restrict__ vlw, const float* __restrict__ vlb)
{
    extern __shared__ float smf[];
    u32*  AsHi  = (u32*)smf;                 // [128][100]
    u32*  AsLo  = AsHi + 12800;
    float* kvbuf = smf + 25600;              // [128][66]
    float* sqb   = kvbuf + 128 * 66;         // 576
    float* sln   = sqb + 576;                // klw|klb|vlw|vlb each 192

    const int tid  = threadIdx.x;
    const int lane = tid & 31, warp = tid >> 5;
    const int rg = warp & 7, ch = warp >> 3;
    const int tig = lane & 3, gid = lane >> 2;
    const size_t R0 = (size_t)blockIdx.x * 128;
    const int b   = blockIdx.x >> 9;
    const int blk = blockIdx.x & (NBLK - 1);

    for (int i = tid; i < 576; i += 512) sqb[i] = qkv_b[i];
    for (int i = tid; i < 192; i += 512) {
        sln[i] = klw[i]; sln[192 + i] = klb[i];
        sln[384 + i] = vlw[i]; sln[576 + i] = vlb[i];
    }
    const float2* xsrc = reinterpret_cast<const float2*>(x + R0 * CC);
    for (int i = tid; i < 128 * 96; i += 512) {
        int r = i / 96, c = i - r * 96;
        float2 v = xsrc[i];
        __nv_bfloat16 h0, l0, h1, l1;
        split_bf16(v.x, h0, l0); split_bf16(v.y, h1, l1);
        AsHi[r * 100 + c] = ((u32)__bfloat16_as_ushort(h1) << 16) | __bfloat16_as_ushort(h0);
        AsLo[r * 100 + c] = ((u32)__bfloat16_as_ushort(l1) << 16) | __bfloat16_as_ushort(l0);
    }
    __syncthreads();

    const int arow = rg * 16 + gid;
    const u32* AH0 = AsHi + arow * 100;
    const u32* AH8 = AsHi + (arow + 8) * 100;
    const u32* AL0 = AsLo + arow * 100;
    const u32* AL8 = AsLo + (arow + 8) * 100;

    for (int h = 0; h < NHEADS; ++h) {
        float acc[6][4];
        #pragma unroll
        for (int nt = 0; nt < 6; ++nt)
            #pragma unroll
            for (int e = 0; e < 4; ++e) acc[nt][e] = 0.0f;

        const ulonglong2* fh =
            reinterpret_cast<const ulonglong2*>(g_fq + (size_t)h * (12 * 12 * 32 * 2))
            + lane;
        // preload kt=0 fragments
        ulonglong2 fA[6];
        #pragma unroll
        for (int nt = 0; nt < 6; ++nt)
            fA[nt] = fh[((ch * 6 + nt) * 12 + 0) * 32];

        #pragma unroll
        for (int kt = 0; kt < 12; ++kt) {
            int kb = kt * 8 + tig;
            u32 ah[4] = { AH0[kb], AH8[kb], AH0[kb + 4], AH8[kb + 4] };
            u32 al[4] = { AL0[kb], AL8[kb], AL0[kb + 4], AL8[kb + 4] };
            // prefetch next kt while issuing this kt's MMAs
            ulonglong2 fN[6];
            int ktn = (kt < 11) ? kt + 1 : kt;
            #pragma unroll
            for (int nt = 0; nt < 6; ++nt)
                fN[nt] = fh[((ch * 6 + nt) * 12 + ktn) * 32];
            #pragma unroll
            for (int nt = 0; nt < 6; ++nt)
                mma3(acc[nt], ah, al, fA[nt]);
            #pragma unroll
            for (int nt = 0; nt < 6; ++nt) fA[nt] = fN[nt];
        }
        __syncthreads();   // previous head's kv-outer finished reading kvbuf

        #pragma unroll
        for (int nt = 0; nt < 6; ++nt) {
            int col = ch * 48 + nt * 8 + 2 * tig;
            float b0 = sqb[96 * h + col], b1 = sqb[96 * h + col + 1];
            float c0 = acc[nt][0] + b0, c1 = acc[nt][1] + b1;
            float c2 = acc[nt][2] + b0, c3 = acc[nt][3] + b1;
            if (col < 32) {
                float* q0 = g_q + (R0 + arow) * CC + h * HC + col;
                float* q8 = g_q + (R0 + arow + 8) * CC + h * HC + col;
                *reinterpret_cast<float2*>(q0) = make_float2(c0, c1);
                *reinterpret_cast<float2*>(q8) = make_float2(c2, c3);
            } else {
                int kc = col - 32;
                *reinterpret_cast<float2*>(kvbuf + arow * 66 + kc)       = make_float2(c0, c1);
                *reinterpret_cast<float2*>(kvbuf + (arow + 8) * 66 + kc) = make_float2(c2, c3);
            }
        }
        __syncthreads();

        if (tid < 256) {
            int row = tid & 127, isv = tid >> 7;
            float* p = kvbuf + row * 66 + isv * 32;
            const float* lw = sln + isv * 384 + h * HC;
            const float* lb = lw + 192;
            float s = 0.0f;
            #pragma unroll
            for (int i = 0; i < 32; ++i) s += p[i];
            float mean = s * (1.0f / 32.0f), vs = 0.0f;
            #pragma unroll
            for (int i = 0; i < 32; ++i) { float d = p[i] - mean; vs = fmaf(d, d, vs); }
            float inv = 1.0f / (sqrtf(vs * (1.0f / 31.0f)) + 1e-5f);
            #pragma unroll
            for (int i = 0; i < 32; ++i)
                p[i] = fmaf(lw[i], (p[i] - mean) * inv, lb[i]);
        }
        __syncthreads();

        {
            int d  = tid >> 4;
            int e0 = (tid & 15) << 1;
            u64 s01 = 0ull;
            for (int r = 0; r < 128; ++r) {
                u64 kk = pack2dup(kvbuf[r * 66 + d]);
                u64 vv = *reinterpret_cast<const u64*>(kvbuf + r * 66 + 32 + e0);
                fma2(s01, kk, vv);
            }
            float2 a = unpack2(s01);
            float* dst = g_kvp + ((size_t)((b * NHEADS) + h) * NBLK + blk) * 1024
                       + d * HC + e0;
            *reinterpret_cast<float2*>(dst) = make_float2(a.x, a.y);
        }
    }
}

// ====================== k_attn (qs padded to stride 194: kills 4-way LDS
// conflict — rq row-groups now land on banks {0,8,16,24}) ===================
#define QSTRIDE 194

__global__ __launch_bounds__(384) void k_attn(const float* __restrict__ x)
{
    __shared__ float kvs[NHEADS * HC * HC];
    __shared__ float qs[32 * QSTRIDE];

    const int tid = threadIdx.x;
    const int R0  = blockIdx.x * 32;
    const int b   = R0 >> 16;

    for (int i = tid; i < NHEADS * HC * HC; i += 384)
        kvs[i] = g_kv[b * (NHEADS * HC * HC) + i] * (1.0f / (float)NN);
    const float* qsrc = g_q + (size_t)R0 * CC;
    for (int i = tid; i < 32 * CC; i += 384) {
        int r = i / CC, c = i - r * CC;
        qs[r * QSTRIDE + c] = qsrc[i];
    }
    __syncthreads();

    const int half = tid / 192;
    const int t    = tid - half * 192;
    const int h    = t >> 5;
    const int t32  = t & 31;
    const int rq   = t32 >> 3;
    const int eq   = t32 & 7;
    const int rbase = half * 16 + rq * 4;

    u64 acc[4][2];
    #pragma unroll
    for (int i = 0; i < 4; ++i) { acc[i][0] = 0ull; acc[i][1] = 0ull; }

    const float* qb = qs + rbase * QSTRIDE + h * HC;
    #pragma unroll 4
    for (int d = 0; d < 32; ++d) {
        const u64* kvp = reinterpret_cast<const u64*>(kvs + (h * HC + d) * HC + eq * 4);
        u64 kv01 = kvp[0], kv23 = kvp[1];
        #pragma unroll
        for (int i = 0; i < 4; ++i) {
            u64 qd = pack2dup(qb[i * QSTRIDE + d]);
            fma2(acc[i][0], qd, kv01);
            fma2(acc[i][1], qd, kv23);
        }
    }
    #pragma unroll
    for (int i = 0; i < 4; ++i) {
        size_t g = ((size_t)(R0 + rbase + i)) * CC + h * HC + eq * 4;
        float4 xv = *reinterpret_cast<const float4*>(x + g);
        float2 a = unpack2(acc[i][0]), c2 = unpack2(acc[i][1]);
        float o0 = a.x + xv.x, o1 = a.y + xv.y, o2 = c2.x + xv.z, o3 = c2.y + xv.w;
        __nv_bfloat16 h0, l0, h1, l1, h2, l2, h3, l3;
        split_bf16(o0, h0, l0); split_bf16(o1, h1, l1);
        split_bf16(o2, h2, l2); split_bf16(o3, h3, l3);
        *reinterpret_cast<__nv_bfloat162*>(g_ret_hi + g)     = __halves2bfloat162(h0, h1);
        *reinterpret_cast<__nv_bfloat162*>(g_ret_hi + g + 2) = __halves2bfloat162(h2, h3);
        *reinterpret_cast<__nv_bfloat162*>(g_ret_lo + g)     = __halves2bfloat162(l0, l1);
        *reinterpret_cast<__nv_bfloat162*>(g_ret_lo + g + 2) = __halves2bfloat162(l2, l3);
    }
}

// ====================== MLP GEMMs via mma.sync (pipelined) =================
#define MS_TOT ((12800 + 12800 + 192) * 4)   /* 103168 B */

__device__ __forceinline__ void mlp_body(
    const __nv_bfloat16* __restrict__ Ahi, const __nv_bfloat16* __restrict__ Alo,
    const u64* __restrict__ frag, const float* __restrict__ bias, bool gelu,
    __nv_bfloat16* __restrict__ OHi, __nv_bfloat16* __restrict__ OLo,
    const float* __restrict__ xres, float* __restrict__ Ofp)
{
    extern __shared__ float smf[];
    u32*  AsHi = (u32*)smf;            // [128][100]
    u32*  AsLo = AsHi + 12800;
    float* sbv = smf + 25600;          // 192 floats

    const int tid  = threadIdx.x;
    const int lane = tid & 31, warp = tid >> 5;
    const int rg = warp & 7, ch = warp >> 3;
    const int tig = lane & 3, gid = lane >> 2;
    const size_t R0 = (size_t)blockIdx.x * 128;

    if (tid < 192) sbv[tid] = bias[tid];
    for (int i = tid; i < 128 * 24; i += 512) {
        int r = i / 24, c4 = i - r * 24;
        uint4 vh = reinterpret_cast<const uint4*>(Ahi + (R0 + r) * CC)[c4];
        uint4 vl = reinterpret_cast<const uint4*>(Alo + (R0 + r) * CC)[c4];
        reinterpret_cast<uint4*>(AsHi + r * 100)[c4] = vh;
        reinterpret_cast<uint4*>(AsLo + r * 100)[c4] = vl;
    }
    __syncthreads();

    const int arow = rg * 16 + gid;
    const u32* AH0 = AsHi + arow * 100;
    const u32* AH8 = AsHi + (arow + 8) * 100;
    const u32* AL0 = AsLo + arow * 100;
    const u32* AL8 = AsLo + (arow + 8) * 100;

    float acc[12][4];
    #pragma unroll
    for (int nt = 0; nt < 12; ++nt)
        #pragma unroll
        for (int e = 0; e < 4; ++e) acc[nt][e] = 0.0f;

    const ulonglong2* fr = reinterpret_cast<const ulonglong2*>(frag) + lane;
    // preload kt=0 first half (nt 0..5)
    ulonglong2 fA[6];
    #pragma unroll
    for (int nt = 0; nt < 6; ++nt)
        fA[nt] = fr[((ch * 12 + nt) * 12 + 0) * 32];

    #pragma unroll
    for (int kt = 0; kt < 12; ++kt) {
        int kb = kt * 8 + tig;
        u32 ah[4] = { AH0[kb], AH8[kb], AH0[kb + 4], AH8[kb + 4] };
        u32 al[4] = { AL0[kb], AL8[kb], AL0[kb + 4], AL8[kb + 4] };
        // load second half (nt 6..11) of this kt
        ulonglong2 fB[6];
        #pragma unroll
        for (int nt = 0; nt < 6; ++nt)
            fB[nt] = fr[((ch * 12 + 6 + nt) * 12 + kt) * 32];
        // MMA first half while fB in flight
        #pragma unroll
        for (int nt = 0; nt < 6; ++nt)
            mma3(acc[nt], ah, al, fA[nt]);
        // prefetch next kt's first half
        ulonglong2 fN[6];
        int ktn = (kt < 11) ? kt + 1 : kt;
        #pragma unroll
        for (int nt = 0; nt < 6; ++nt)
            fN[nt] = fr[((ch * 12 + nt) * 12 + ktn) * 32];
        // MMA second half while fN in flight
        #pragma unroll
        for (int nt = 0; nt < 6; ++nt)
            mma3(acc[6 + nt], ah, al, fB[nt]);
        #pragma unroll
        for (int nt = 0; nt < 6; ++nt) fA[nt] = fN[nt];
    }

    #pragma unroll
    for (int nt = 0; nt < 12; ++nt) {
        int col = ch * 96 + nt * 8 + 2 * tig;
        float b0 = sbv[col], b1 = sbv[col + 1];
        float v0 = acc[nt][0] + b0, v1 = acc[nt][1] + b1;
        float v2 = acc[nt][2] + b0, v3 = acc[nt][3] + b1;
        size_t g0 = (R0 + arow) * CC + col;
        size_t g8 = (R0 + arow + 8) * CC + col;
        if (gelu) {
            float e0 = 0.5f * v0 * (1.0f + erff(v0 * 0.70710678118654752440f));
            float e1 = 0.5f * v1 * (1.0f + erff(v1 * 0.70710678118654752440f));
            float e2 = 0.5f * v2 * (1.0f + erff(v2 * 0.70710678118654752440f));
            float e3 = 0.5f * v3 * (1.0f + erff(v3 * 0.70710678118654752440f));
            __nv_bfloat16 h0, l0, h1, l1, h2, l2, h3, l3;
            split_bf16(e0, h0, l0); split_bf16(e1, h1, l1);
            split_bf16(e2, h2, l2); split_bf16(e3, h3, l3);
            *reinterpret_cast<u32*>(OHi + g0) = ((u32)__bfloat16_as_ushort(h1) << 16) | __bfloat16_as_ushort(h0);
            *reinterpret_cast<u32*>(OLo + g0) = ((u32)__bfloat16_as_ushort(l1) << 16) | __bfloat16_as_ushort(l0);
            *reinterpret_cast<u32*>(OHi + g8) = ((u32)__bfloat16_as_ushort(h3) << 16) | __bfloat16_as_ushort(h2);
            *reinterpret_cast<u32*>(OLo + g8) = ((u32)__bfloat16_as_ushort(l3) << 16) | __bfloat16_as_ushort(l2);
        } else {
            float2 x0 = *reinterpret_cast<const float2*>(xres + g0);
            float2 x8 = *reinterpret_cast<const float2*>(xres + g8);
            *reinterpret_cast<float2*>(Ofp + g0) = make_float2(v0 + x0.x, v1 + x0.y);
            *reinterpret_cast<float2*>(Ofp + g8) = make_float2(v2 + x8.x, v3 + x8.y);
        }
    }
}

__global__ __launch_bounds__(512) void k_mlp1(const float* __restrict__ b) {
    mlp_body(g_ret_hi, g_ret_lo, g_f1, b, true, g_h_hi, g_h_lo, nullptr, nullptr);
}
__global__ __launch_bounds__(512) void k_mlp2(const float* __restrict__ b,
                                              const float* __restrict__ x,
                                              float* __restrict__ out) {
    mlp_body(g_h_hi, g_h_lo, g_f2, b, false, nullptr, nullptr, x, out);
}

// ---------------------------------------------------------------------------
extern "C" void kernel_launch(void* const* d_in, const int* in_sizes, int n_in,
                              void* d_out, int out_size)
{
    (void)in_sizes; (void)n_in; (void)out_size;
    const float* x     = (const float*)d_in[0];
    const float* qkv_w = (const float*)d_in[1];
    const float* qkv_b = (const float*)d_in[2];
    const float* o1_w  = (const float*)d_in[3];
    const float* o1_b  = (const float*)d_in[4];
    const float* o2_w  = (const float*)d_in[5];
    const float* o2_b  = (const float*)d_in[6];
    const float* klw   = (const float*)d_in[7];
    const float* klb   = (const float*)d_in[8];
    const float* vlw   = (const float*)d_in[9];
    const float* vlb   = (const float*)d_in[10];
    float* out = (float*)d_out;

    cudaFuncSetAttribute(k_qkv,  cudaFuncAttributeMaxDynamicSharedMemorySize, QS_TOT);
    cudaFuncSetAttribute(k_mlp1, cudaFuncAttributeMaxDynamicSharedMemorySize, MS_TOT);
    cudaFuncSetAttribute(k_mlp2, cudaFuncAttributeMaxDynamicSharedMemorySize, MS_TOT);

    k_prep<<<360, 256>>>(qkv_w, o1_w, o2_w);

    k_qkv<<<BN / 128, 512, QS_TOT>>>(x, qkv_b, klw, klb, vlw, vlb);
    k_kvred<<<Bb * NHEADS, 1024>>>();
    k_attn<<<BN / 32, 384>>>(x);
    k_mlp1<<<BN / 128, 512, MS_TOT>>>(o1_b);
    k_mlp2<<<BN / 128, 512, MS_TOT>>>(o2_b, x, out);
}